// round 1
// baseline (speedup 1.0000x reference)
#include <cuda_runtime.h>
#include <math.h>

#define Bb 2
#define Ls 2048
#define Ds 1024
#define Hh 16
#define HDd 64
#define FFs 4096
#define BLn (Bb*Ls)   // 4096
#define EPSf 1e-5f

// ---------------- scratch (static device memory; no allocations) ----------------
__device__ float g_stage[BLn*Ds];
__device__ float g_q[BLn*Ds];
__device__ float g_k[BLn*Ds];
__device__ float g_v[BLn*Ds];
__device__ float g_attn[BLn*Ds];
__device__ float g_tgt2[BLn*Ds];
__device__ float g_mem[BLn*Ds];
__device__ float g_ln[BLn*Ds];
__device__ float g_h2[BLn*2*Ds];
__device__ float g_glu[BLn*Ds];
__device__ float g_dw[BLn*Ds];
__device__ float g_conv[BLn*Ds];
__device__ float g_pwT[Ls*Ls];
__device__ float g_proj[BLn*Ds];
__device__ float g_mem2[BLn*Ds];
__device__ float g_ffn[BLn*FFs];
__device__ float g_sum[BLn*Ds];

// ---------------- generic SGEMM: C = A(MxK) @ B(KxN) + bias (+ add) ----------------
// bias_mode: 0 none, 1 per-column bias[n], 2 per-row bias[m]
__global__ __launch_bounds__(256) void sgemm_kernel(
    const float* __restrict__ A, const float* __restrict__ B,
    const float* __restrict__ bias, const float* __restrict__ addp,
    float* __restrict__ C, int M, int N, int K,
    long sA, long sB, long sC, int bias_mode)
{
    A += (long)blockIdx.z * sA;
    B += (long)blockIdx.z * sB;
    C += (long)blockIdx.z * sC;
    const float* addb = addp ? addp + (long)blockIdx.z * sC : (const float*)0;

    __shared__ float As[8][128];
    __shared__ float Bs[8][128];
    int tid = threadIdx.x;
    int bm = blockIdx.y * 128, bn = blockIdx.x * 128;

    int arow = tid >> 1;
    int acol = (tid & 1) * 4;
    int brow = tid >> 5;
    int bcol = (tid & 31) * 4;

    int tm = (tid >> 4) * 8;
    int tn = (tid & 15) * 8;

    float acc[8][8];
#pragma unroll
    for (int i = 0; i < 8; i++)
#pragma unroll
        for (int j = 0; j < 8; j++) acc[i][j] = 0.f;

    const float* Aptr = A + (long)(bm + arow) * K + acol;
    const float* Bptr = B + (long)brow * N + bn + bcol;

    for (int k0 = 0; k0 < K; k0 += 8) {
        float4 av = *(const float4*)(Aptr + k0);
        As[acol + 0][arow] = av.x;
        As[acol + 1][arow] = av.y;
        As[acol + 2][arow] = av.z;
        As[acol + 3][arow] = av.w;
        float4 bv = *(const float4*)(Bptr + (long)k0 * N);
        *(float4*)&Bs[brow][bcol] = bv;
        __syncthreads();
#pragma unroll
        for (int kk = 0; kk < 8; kk++) {
            float4 a0 = *(const float4*)&As[kk][tm];
            float4 a1 = *(const float4*)&As[kk][tm + 4];
            float4 b0 = *(const float4*)&Bs[kk][tn];
            float4 b1 = *(const float4*)&Bs[kk][tn + 4];
            float a[8] = {a0.x, a0.y, a0.z, a0.w, a1.x, a1.y, a1.z, a1.w};
            float b[8] = {b0.x, b0.y, b0.z, b0.w, b1.x, b1.y, b1.z, b1.w};
#pragma unroll
            for (int i = 0; i < 8; i++)
#pragma unroll
                for (int j = 0; j < 8; j++)
                    acc[i][j] = fmaf(a[i], b[j], acc[i][j]);
        }
        __syncthreads();
    }

#pragma unroll
    for (int i = 0; i < 8; i++) {
        long row = bm + tm + i;
        float brow_v = (bias_mode == 2) ? bias[row] : 0.f;
        float* crow = C + row * (long)N + bn + tn;
        const float* arow_p = addb ? addb + row * (long)N + bn + tn : (const float*)0;
#pragma unroll
        for (int jj = 0; jj < 8; jj += 4) {
            float v[4];
#pragma unroll
            for (int c = 0; c < 4; c++) {
                float val = acc[i][jj + c];
                if (bias_mode == 1) val += bias[bn + tn + jj + c];
                else if (bias_mode == 2) val += brow_v;
                if (arow_p) val += arow_p[jj + c];
                v[c] = val;
            }
            float4 o = {v[0], v[1], v[2], v[3]};
            *(float4*)(crow + jj) = o;
        }
    }
}

// ---------------- RoPE ----------------
__device__ __forceinline__ float rope_pval(int l, int m)
{
    int i = (m < 32) ? m : m - 32;
    float inv = powf(10000.f, -(float)(2 * i) / 64.f);
    float ang = (float)l * inv;
    return (m < 32) ? cosf(ang) : sinf(ang);
}

__global__ __launch_bounds__(256) void rope_kernel(const float* __restrict__ in, float* __restrict__ out)
{
    int idx = blockIdx.x * blockDim.x + threadIdx.x;  // B*L*H*32
    if (idx >= Bb * Ls * Hh * 32) return;
    int j = idx & 31;
    int h = (idx >> 5) & (Hh - 1);
    int bl = idx >> 9;
    int l = bl & (Ls - 1);
    long base = (long)bl * Ds + h * HDd;
    float xe = in[base + 2 * j];
    float xo = in[base + 2 * j + 1];
    float c = rope_pval(l, 2 * j);
    float s = rope_pval(l, 2 * j + 1);
    out[base + j] = xe * c - xo * s;
    out[base + 32 + j] = xe * s + xo * c;
}

// ---------------- fused attention (flash-style, ALiBi, HD=64) ----------------
#define ATTN_SMEM_FLOATS (64*64 + 3*64*68 + 64)

__global__ __launch_bounds__(256) void attn_kernel(
    const float* __restrict__ Q, const float* __restrict__ Kp,
    const float* __restrict__ Vp, float* __restrict__ O)
{
    extern __shared__ float sm[];
    float* sq = sm;                  // 64 x 64 (stride 64)
    float* sk = sq + 64 * 64;        // 64 x 68
    float* sv = sk + 64 * 68;        // 64 x 68
    float* ss = sv + 64 * 68;        // 64 x 68
    float* salpha = ss + 64 * 68;    // 64

    int tid = threadIdx.x;
    int bh = blockIdx.y;
    int b = bh >> 4;
    int h = bh & 15;
    int q0 = blockIdx.x * 64;
    int hb = h * HDd;
    float slope = exp2f(-0.5f * (float)h);

    // load q tile
    {
        int r = tid >> 4;
        int d0 = (tid & 15) * 4;
#pragma unroll
        for (int cc = 0; cc < 4; cc++) {
            int rr = r + cc * 16;
            float4 v = *(const float4*)&Q[((long)(b * Ls + q0 + rr)) * Ds + hb + d0];
            *(float4*)&sq[rr * 64 + d0] = v;
        }
    }

    int ty = tid >> 4, tx = tid & 15;
    int r0 = ty * 4, c0 = tx * 4;
    int srow = tid >> 2, spart = tid & 3;

    float acc_o[4][4];
#pragma unroll
    for (int i = 0; i < 4; i++)
#pragma unroll
        for (int j = 0; j < 4; j++) acc_o[i][j] = 0.f;

    float mrow = -1e30f, lrow = 0.f;

    for (int k0 = 0; k0 < Ls; k0 += 64) {
        __syncthreads();  // protect sk/sv/ss from previous iteration readers (and sq before first use)
        {
            int c = tid >> 4;
            int d0 = (tid & 15) * 4;
#pragma unroll
            for (int cc = 0; cc < 4; cc++) {
                int rr = c + cc * 16;
                long gidx = ((long)(b * Ls + k0 + rr)) * Ds + hb + d0;
                *(float4*)&sk[rr * 68 + d0] = *(const float4*)&Kp[gidx];
                *(float4*)&sv[rr * 68 + d0] = *(const float4*)&Vp[gidx];
            }
        }
        __syncthreads();

        // S = q @ k^T
        float acc[4][4];
#pragma unroll
        for (int i = 0; i < 4; i++)
#pragma unroll
            for (int j = 0; j < 4; j++) acc[i][j] = 0.f;

#pragma unroll 4
        for (int d0 = 0; d0 < 64; d0 += 4) {
            float4 a4[4], b4[4];
#pragma unroll
            for (int i = 0; i < 4; i++) a4[i] = *(const float4*)&sq[(r0 + i) * 64 + d0];
#pragma unroll
            for (int j = 0; j < 4; j++) b4[j] = *(const float4*)&sk[(c0 + j) * 68 + d0];
#pragma unroll
            for (int i = 0; i < 4; i++) {
                float ax = a4[i].x, ay = a4[i].y, az = a4[i].z, aw = a4[i].w;
#pragma unroll
                for (int j = 0; j < 4; j++) {
                    acc[i][j] = fmaf(ax, b4[j].x, acc[i][j]);
                    acc[i][j] = fmaf(ay, b4[j].y, acc[i][j]);
                    acc[i][j] = fmaf(az, b4[j].z, acc[i][j]);
                    acc[i][j] = fmaf(aw, b4[j].w, acc[i][j]);
                }
            }
        }
        // scale + alibi, write to ss
#pragma unroll
        for (int i = 0; i < 4; i++) {
            int qi = q0 + r0 + i;
            float vv[4];
#pragma unroll
            for (int j = 0; j < 4; j++) {
                int kj = k0 + c0 + j;
                vv[j] = acc[i][j] * 0.125f + slope * fmaxf((float)(qi - kj), 0.f);
            }
            float4 w = {vv[0], vv[1], vv[2], vv[3]};
            *(float4*)&ss[(r0 + i) * 68 + c0] = w;
        }
        __syncthreads();

        // online softmax stats: 4 threads per row
        {
            int cbase = spart * 16;
            float tmax = -1e30f;
#pragma unroll
            for (int c = 0; c < 16; c++) tmax = fmaxf(tmax, ss[srow * 68 + cbase + c]);
            tmax = fmaxf(tmax, __shfl_xor_sync(0xffffffffu, tmax, 1));
            tmax = fmaxf(tmax, __shfl_xor_sync(0xffffffffu, tmax, 2));
            float mnew = fmaxf(mrow, tmax);
            float alpha = __expf(mrow - mnew);
            float psum = 0.f;
#pragma unroll
            for (int c = 0; c < 16; c++) {
                float p = __expf(ss[srow * 68 + cbase + c] - mnew);
                ss[srow * 68 + cbase + c] = p;
                psum += p;
            }
            psum += __shfl_xor_sync(0xffffffffu, psum, 1);
            psum += __shfl_xor_sync(0xffffffffu, psum, 2);
            lrow = lrow * alpha + psum;
            mrow = mnew;
            if (spart == 0) salpha[srow] = alpha;
        }
        __syncthreads();

        // O = O*alpha + P @ V    (thread owns rows r0..r0+3, dims c0..c0+3)
        {
            float al[4];
#pragma unroll
            for (int i = 0; i < 4; i++) al[i] = salpha[r0 + i];
#pragma unroll
            for (int i = 0; i < 4; i++)
#pragma unroll
                for (int j = 0; j < 4; j++) acc_o[i][j] *= al[i];

#pragma unroll 4
            for (int cc0 = 0; cc0 < 64; cc0 += 4) {
                float4 p4[4], v4[4];
#pragma unroll
                for (int i = 0; i < 4; i++) p4[i] = *(const float4*)&ss[(r0 + i) * 68 + cc0];
#pragma unroll
                for (int c = 0; c < 4; c++) v4[c] = *(const float4*)&sv[(cc0 + c) * 68 + c0];
                float vb[4][4] = {
                    {v4[0].x, v4[0].y, v4[0].z, v4[0].w},
                    {v4[1].x, v4[1].y, v4[1].z, v4[1].w},
                    {v4[2].x, v4[2].y, v4[2].z, v4[2].w},
                    {v4[3].x, v4[3].y, v4[3].z, v4[3].w}};
#pragma unroll
                for (int i = 0; i < 4; i++) {
                    float px = p4[i].x, py = p4[i].y, pz = p4[i].z, pw = p4[i].w;
#pragma unroll
                    for (int j = 0; j < 4; j++) {
                        acc_o[i][j] = fmaf(px, vb[0][j], acc_o[i][j]);
                        acc_o[i][j] = fmaf(py, vb[1][j], acc_o[i][j]);
                        acc_o[i][j] = fmaf(pz, vb[2][j], acc_o[i][j]);
                        acc_o[i][j] = fmaf(pw, vb[3][j], acc_o[i][j]);
                    }
                }
            }
        }
    }

    __syncthreads();
    if (spart == 0) salpha[srow] = 1.f / lrow;
    __syncthreads();
#pragma unroll
    for (int i = 0; i < 4; i++) {
        float inv = salpha[r0 + i];
        float4 w = {acc_o[i][0] * inv, acc_o[i][1] * inv, acc_o[i][2] * inv, acc_o[i][3] * inv};
        *(float4*)&O[((long)(b * Ls + q0 + r0 + i)) * Ds + hb + c0] = w;
    }
}

// ---------------- LayerNorm (optional residual added AFTER ln) ----------------
__global__ __launch_bounds__(256) void ln_kernel(
    const float* __restrict__ x, const float* __restrict__ g, const float* __restrict__ bb,
    const float* __restrict__ res, float* __restrict__ out)
{
    int row = blockIdx.x;
    const float* xr = x + (long)row * Ds;
    __shared__ float sx[Ds];
    __shared__ float sred[8];
    __shared__ float s_mean, s_rstd;
    int tid = threadIdx.x;

    float s = 0.f;
    for (int i = tid; i < Ds; i += 256) {
        float v = xr[i];
        sx[i] = v;
        s += v;
    }
#pragma unroll
    for (int o = 16; o > 0; o >>= 1) s += __shfl_down_sync(0xffffffffu, s, o);
    if ((tid & 31) == 0) sred[tid >> 5] = s;
    __syncthreads();
    if (tid == 0) {
        float t = 0.f;
        for (int i = 0; i < 8; i++) t += sred[i];
        s_mean = t / (float)Ds;
    }
    __syncthreads();
    float m = s_mean;
    float vs = 0.f;
    for (int i = tid; i < Ds; i += 256) {
        float d = sx[i] - m;
        vs += d * d;
    }
#pragma unroll
    for (int o = 16; o > 0; o >>= 1) vs += __shfl_down_sync(0xffffffffu, vs, o);
    if ((tid & 31) == 0) sred[tid >> 5] = vs;
    __syncthreads();
    if (tid == 0) {
        float t = 0.f;
        for (int i = 0; i < 8; i++) t += sred[i];
        s_rstd = rsqrtf(t / (float)Ds + EPSf);
    }
    __syncthreads();
    float rs = s_rstd;
    for (int i = tid; i < Ds; i += 256) {
        float v = (sx[i] - m) * rs * g[i] + bb[i];
        if (res) v += res[(long)row * Ds + i];
        out[(long)row * Ds + i] = v;
    }
}

// ---------------- GLU ----------------
__global__ __launch_bounds__(256) void glu_kernel(const float* __restrict__ h2, float* __restrict__ out)
{
    long idx = (long)blockIdx.x * blockDim.x + threadIdx.x;
    if (idx >= (long)BLn * Ds) return;
    long row = idx / Ds;
    int d = (int)(idx % Ds);
    float a = h2[row * 2 * Ds + d];
    float bgate = h2[row * 2 * Ds + Ds + d];
    out[idx] = a * (1.f / (1.f + expf(-bgate)));
}

// ---------------- depthwise conv + bn affine + hardswish ----------------
__global__ __launch_bounds__(256) void dwconv_kernel(
    const float* __restrict__ in, const float* __restrict__ w, const float* __restrict__ wb,
    const float* __restrict__ bng, const float* __restrict__ bnb, float* __restrict__ out)
{
    long idx = (long)blockIdx.x * blockDim.x + threadIdx.x;
    if (idx >= (long)BLn * Ds) return;
    long row = idx / Ds;
    int d = (int)(idx % Ds);
    int b = (int)(row / Ls);
    int l = (int)(row % Ls);
    float acc = 0.f;
#pragma unroll
    for (int m = 0; m < 5; m++) {
        int ls = l + 2 - m;
        if (ls >= 0 && ls < Ls)
            acc = fmaf(w[d * 5 + m], in[((long)b * Ls + ls) * Ds + d], acc);
    }
    float bnscale = rsqrtf(1.f + EPSf);
    float y = (acc + wb[d]) * bnscale * bng[d] + bnb[d];
    float r6 = fminf(fmaxf(y + 3.f, 0.f), 6.f);
    out[idx] = y * r6 * (1.f / 6.f);
}

// ---------------- add broadcast row 0 (per batch) ----------------
__global__ __launch_bounds__(256) void addrow0_kernel(float* __restrict__ io, const float* __restrict__ mem)
{
    long idx = (long)blockIdx.x * blockDim.x + threadIdx.x;
    if (idx >= (long)BLn * Ds) return;
    long row = idx / Ds;
    int d = (int)(idx % Ds);
    int b = (int)(row / Ls);
    io[idx] += mem[(long)b * Ls * Ds + d];
}

// ---------------- exact GELU (in-place) ----------------
__global__ __launch_bounds__(256) void gelu_kernel(float* __restrict__ x, long n)
{
    long idx = (long)blockIdx.x * blockDim.x + threadIdx.x;
    if (idx >= n) return;
    float v = x[idx];
    x[idx] = 0.5f * v * (1.f + erff(v * 0.70710678118654752f));
}

// ---------------- transpose (LxL) ----------------
__global__ void transpose_kernel(const float* __restrict__ in, float* __restrict__ out, int n)
{
    __shared__ float t[32][33];
    int x = blockIdx.x * 32 + threadIdx.x;
    int y = blockIdx.y * 32 + threadIdx.y;
#pragma unroll
    for (int j = 0; j < 32; j += 8)
        t[threadIdx.y + j][threadIdx.x] = in[(long)(y + j) * n + x];
    __syncthreads();
    x = blockIdx.y * 32 + threadIdx.x;
    y = blockIdx.x * 32 + threadIdx.y;
#pragma unroll
    for (int j = 0; j < 32; j += 8)
        out[(long)(y + j) * n + x] = t[threadIdx.x][threadIdx.y + j];
}

// ---------------- host side ----------------
static void gemm(const float* A, const float* B, const float* bias, const float* add,
                 float* C, int M, int N, int K, int batch,
                 long sA, long sB, long sC, int bias_mode)
{
    dim3 grid(N / 128, M / 128, batch);
    sgemm_kernel<<<grid, 256>>>(A, B, bias, add, C, M, N, K, sA, sB, sC, bias_mode);
}

extern "C" void kernel_launch(void* const* d_in, const int* in_sizes, int n_in,
                              void* d_out, int out_size)
{
    const float* memory = (const float*)d_in[0];
    const float* wq = (const float*)d_in[1];
    const float* bq = (const float*)d_in[2];
    const float* wk = (const float*)d_in[3];
    const float* bk = (const float*)d_in[4];
    const float* wv = (const float*)d_in[5];
    const float* bv = (const float*)d_in[6];
    const float* wo = (const float*)d_in[7];
    const float* bo = (const float*)d_in[8];
    const float* n1_g = (const float*)d_in[9];
    const float* n1_b = (const float*)d_in[10];
    const float* cln_g = (const float*)d_in[11];
    const float* cln_b = (const float*)d_in[12];
    const float* pw1_w = (const float*)d_in[13];
    const float* pw1_b = (const float*)d_in[14];
    const float* dw_w = (const float*)d_in[15];
    const float* dw_b = (const float*)d_in[16];
    const float* bn_g = (const float*)d_in[17];
    const float* bn_b = (const float*)d_in[18];
    const float* pw2_w = (const float*)d_in[19];
    const float* pw2_b = (const float*)d_in[20];
    const float* proj_w = (const float*)d_in[21];
    const float* proj_b = (const float*)d_in[22];
    const float* proj2_w = (const float*)d_in[23];
    const float* proj2_b = (const float*)d_in[24];
    const float* lin1_w = (const float*)d_in[25];
    const float* lin1_b = (const float*)d_in[26];
    const float* lin2_w = (const float*)d_in[27];
    const float* lin2_b = (const float*)d_in[28];
    const float* n3_g = (const float*)d_in[29];
    const float* n3_b = (const float*)d_in[30];
    float* out = (float*)d_out;

    float *stage, *q, *k, *v, *attn, *tgt2, *mem, *ln, *h2, *glu, *dw, *conv, *pwT, *proj, *mem2, *ffn, *sum;
    cudaGetSymbolAddress((void**)&stage, g_stage);
    cudaGetSymbolAddress((void**)&q, g_q);
    cudaGetSymbolAddress((void**)&k, g_k);
    cudaGetSymbolAddress((void**)&v, g_v);
    cudaGetSymbolAddress((void**)&attn, g_attn);
    cudaGetSymbolAddress((void**)&tgt2, g_tgt2);
    cudaGetSymbolAddress((void**)&mem, g_mem);
    cudaGetSymbolAddress((void**)&ln, g_ln);
    cudaGetSymbolAddress((void**)&h2, g_h2);
    cudaGetSymbolAddress((void**)&glu, g_glu);
    cudaGetSymbolAddress((void**)&dw, g_dw);
    cudaGetSymbolAddress((void**)&conv, g_conv);
    cudaGetSymbolAddress((void**)&pwT, g_pwT);
    cudaGetSymbolAddress((void**)&proj, g_proj);
    cudaGetSymbolAddress((void**)&mem2, g_mem2);
    cudaGetSymbolAddress((void**)&ffn, g_ffn);
    cudaGetSymbolAddress((void**)&sum, g_sum);

    cudaFuncSetAttribute(attn_kernel, cudaFuncAttributeMaxDynamicSharedMemorySize,
                         ATTN_SMEM_FLOATS * (int)sizeof(float));

    const long eBLD = (long)BLn * Ds;
    int ew_grid = (int)((eBLD + 255) / 256);
    int rope_grid = (Bb * Ls * Hh * 32) / 256;

    // q/k/v projections + RoPE
    gemm(memory, wq, bq, 0, stage, BLn, Ds, Ds, 1, 0, 0, 0, 1);
    rope_kernel<<<rope_grid, 256>>>(stage, q);
    gemm(memory, wk, bk, 0, stage, BLn, Ds, Ds, 1, 0, 0, 0, 1);
    rope_kernel<<<rope_grid, 256>>>(stage, k);
    gemm(memory, wv, bv, 0, v, BLn, Ds, Ds, 1, 0, 0, 0, 1);

    // fused attention
    {
        dim3 grid(Ls / 64, Bb * Hh);
        attn_kernel<<<grid, 256, ATTN_SMEM_FLOATS * sizeof(float)>>>(q, k, v, attn);
    }

    // output projection, residual + LN
    gemm(attn, wo, bo, 0, tgt2, BLn, Ds, Ds, 1, 0, 0, 0, 1);
    ln_kernel<<<BLn, 256>>>(tgt2, n1_g, n1_b, memory, mem);   // mem = memory + LN(tgt2)

    // conv block
    ln_kernel<<<BLn, 256>>>(mem, cln_g, cln_b, 0, ln);
    gemm(ln, pw1_w, pw1_b, 0, h2, BLn, 2 * Ds, Ds, 1, 0, 0, 0, 1);
    glu_kernel<<<ew_grid, 256>>>(h2, glu);
    dwconv_kernel<<<ew_grid, 256>>>(glu, dw_w, dw_b, bn_g, bn_b, dw);
    gemm(dw, pw2_w, pw2_b, 0, conv, BLn, Ds, Ds, 1, 0, 0, 0, 1);
    addrow0_kernel<<<ew_grid, 256>>>(conv, mem);

    // proj branch: out[b,m,d] = sum_l mem[b,l,d]*proj_w[l,m] + proj_b[m]
    {
        dim3 tgrid(Ls / 32, Ls / 32);
        dim3 tblk(32, 8);
        transpose_kernel<<<tgrid, tblk>>>(proj_w, pwT, Ls);
    }
    gemm(pwT, mem, proj_b, 0, proj, Ls, Ds, Ls, Bb, 0, (long)Ls * Ds, (long)Ls * Ds, 2);
    gemm(proj, proj2_w, proj2_b, conv, mem2, BLn, Ds, Ds, 1, 0, 0, 0, 1); // mem2 = proj2 + conv

    // FFN
    gemm(mem2, lin1_w, lin1_b, 0, ffn, BLn, FFs, Ds, 1, 0, 0, 0, 1);
    {
        long n = (long)BLn * FFs;
        gelu_kernel<<<(int)((n + 255) / 256), 256>>>(ffn, n);
    }
    gemm(ffn, lin2_w, lin2_b, mem2, sum, BLn, Ds, FFs, 1, 0, 0, 0, 1);  // sum = mem2 + ffn@lin2+b

    // final LN -> output
    ln_kernel<<<BLn, 256>>>(sum, n3_g, n3_b, 0, out);
}

// round 3
// speedup vs baseline: 1.6880x; 1.6880x over previous
#include <cuda_runtime.h>
#include <cuda_bf16.h>
#include <math.h>

#define Bb 2
#define Ls 2048
#define Ds 1024
#define Hh 16
#define HDd 64
#define FFs 4096
#define BLn (Bb*Ls)
#define EPSf 1e-5f

// ---------------- scratch (static device memory) ----------------
__device__ float g_stage[BLn*Ds];
__device__ float g_q[BLn*Ds];
__device__ float g_k[BLn*Ds];
__device__ float g_v[BLn*Ds];
__device__ float g_attn[BLn*Ds];
__device__ float g_tgt2[BLn*Ds];
__device__ float g_mem[BLn*Ds];
__device__ float g_ln[BLn*Ds];
__device__ float g_h2[BLn*2*Ds];
__device__ float g_glu[BLn*Ds];
__device__ float g_dw[BLn*Ds];
__device__ float g_conv[BLn*Ds];
__device__ float g_pwT[Ls*Ls];
__device__ float g_proj[BLn*Ds];
__device__ float g_mem2[BLn*Ds];
__device__ float g_ffn[BLn*FFs];
__device__ float g_sum[BLn*Ds];
__device__ unsigned short g_ah[16777216];  // bf16 bits, 4096*4096
__device__ unsigned short g_al[16777216];
__device__ unsigned short g_bh[4194304];   // 4096*1024
__device__ unsigned short g_bl[4194304];

// ---------------- split fp32 -> bf16 hi/lo (bit-packed as ushort) ----------------
__global__ __launch_bounds__(256) void split_kernel(
    const float* __restrict__ x, unsigned short* __restrict__ hi,
    unsigned short* __restrict__ lo, long n)
{
    long i = ((long)blockIdx.x * 256 + threadIdx.x) * 4;
    if (i >= n) return;
    float4 v = *(const float4*)(x + i);
    float f0 = v.x, f1 = v.y, f2 = v.z, f3 = v.w;
    __nv_bfloat16 h0 = __float2bfloat16_rn(f0);
    __nv_bfloat16 h1 = __float2bfloat16_rn(f1);
    __nv_bfloat16 h2 = __float2bfloat16_rn(f2);
    __nv_bfloat16 h3 = __float2bfloat16_rn(f3);
    __nv_bfloat16 l0 = __float2bfloat16_rn(f0 - __bfloat162float(h0));
    __nv_bfloat16 l1 = __float2bfloat16_rn(f1 - __bfloat162float(h1));
    __nv_bfloat16 l2 = __float2bfloat16_rn(f2 - __bfloat162float(h2));
    __nv_bfloat16 l3 = __float2bfloat16_rn(f3 - __bfloat162float(h3));
    ushort4 hv;
    hv.x = __bfloat16_as_ushort(h0); hv.y = __bfloat16_as_ushort(h1);
    hv.z = __bfloat16_as_ushort(h2); hv.w = __bfloat16_as_ushort(h3);
    ushort4 lv;
    lv.x = __bfloat16_as_ushort(l0); lv.y = __bfloat16_as_ushort(l1);
    lv.z = __bfloat16_as_ushort(l2); lv.w = __bfloat16_as_ushort(l3);
    *(ushort4*)(hi + i) = hv;
    *(ushort4*)(lo + i) = lv;
}

// ---------------- tensor-core GEMM helpers ----------------
__device__ __forceinline__ unsigned smem_u32(const void* p)
{
    return (unsigned)__cvta_generic_to_shared(p);
}
__device__ __forceinline__ void cp16(unsigned s, const void* g)
{
    asm volatile("cp.async.cg.shared.global [%0], [%1], 16;" :: "r"(s), "l"(g));
}
__device__ __forceinline__ void cp_commit()
{
    asm volatile("cp.async.commit_group;");
}
__device__ __forceinline__ void cp_wait1()
{
    asm volatile("cp.async.wait_group 1;");
}
__device__ __forceinline__ void cp_wait0()
{
    asm volatile("cp.async.wait_group 0;");
}
__device__ __forceinline__ void ldsm4(unsigned& r0, unsigned& r1, unsigned& r2, unsigned& r3, unsigned a)
{
    asm volatile("ldmatrix.sync.aligned.m8n8.x4.shared.b16 {%0,%1,%2,%3}, [%4];"
        : "=r"(r0), "=r"(r1), "=r"(r2), "=r"(r3) : "r"(a));
}
__device__ __forceinline__ void ldsm2t(unsigned& r0, unsigned& r1, unsigned a)
{
    asm volatile("ldmatrix.sync.aligned.m8n8.x2.trans.shared.b16 {%0,%1}, [%2];"
        : "=r"(r0), "=r"(r1) : "r"(a));
}
__device__ __forceinline__ void mma16816(float* d, const unsigned* a, const unsigned* b)
{
    asm volatile("mma.sync.aligned.m16n8k16.row.col.f32.bf16.bf16.f32 "
        "{%0,%1,%2,%3}, {%4,%5,%6,%7}, {%8,%9}, {%0,%1,%2,%3};"
        : "+f"(d[0]), "+f"(d[1]), "+f"(d[2]), "+f"(d[3])
        : "r"(a[0]), "r"(a[1]), "r"(a[2]), "r"(a[3]), "r"(b[0]), "r"(b[1]));
}

// Tile 128x128x32, 256 threads (8 warps: 2 along M x 4 along N), warp tile 64x32.
// smem stage layout (ushort elems): A hi [128][40], A lo [128][40], B hi [32][136], B lo [32][136]
#define LDA_P 40
#define LDB_P 136
#define OFF_AL (128*40)
#define OFF_BH (2*128*40)
#define OFF_BL (2*128*40 + 32*136)
#define STAGE_ELEMS (2*128*40 + 2*32*136)
#define BG_SMEM_BYTES (2*STAGE_ELEMS*2)

__global__ __launch_bounds__(256, 1) void bgemm_kernel(
    const unsigned short* __restrict__ Ah, const unsigned short* __restrict__ Al,
    const unsigned short* __restrict__ Bh, const unsigned short* __restrict__ Bl,
    const float* __restrict__ bias, const float* __restrict__ addp,
    float* __restrict__ C, int M, int N, int K,
    long sB, long sC, int bias_mode)
{
    extern __shared__ unsigned short smem[];
    const int tid = threadIdx.x;
    const int lane = tid & 31;
    const int warp = tid >> 5;
    const int bm = blockIdx.y * 128;
    const int bn = blockIdx.x * 128;
    const unsigned short* Bhz = Bh + (long)blockIdx.z * sB;
    const unsigned short* Blz = Bl + (long)blockIdx.z * sB;
    float* Cz = C + (long)blockIdx.z * sC;
    const float* addz = addp ? (addp + (long)blockIdx.z * sC) : (const float*)0;
    const int m0 = (warp & 1) * 64;
    const int n0 = (warp >> 1) * 32;

    // per-thread load coords
    const int ar0 = tid >> 1;             // 0..127  A row
    const int ac0 = (tid & 1) * 16;       // 0 or 16 (two 8-elem chunks per row half)
    const int br0 = tid >> 4;             // 0..15   B row pair base
    const int bc0 = (tid & 15) * 8;       // 0..120

    float acc[4][4][4];
#pragma unroll
    for (int mi = 0; mi < 4; mi++)
#pragma unroll
        for (int ni = 0; ni < 4; ni++)
#pragma unroll
            for (int qq = 0; qq < 4; qq++) acc[mi][ni][qq] = 0.f;

    const int nIter = K >> 5;

#pragma unroll 1
    for (int it = 0; it < nIter + 1; ++it) {
        if (it < nIter) {
            unsigned short* st = smem + (it & 1) * STAGE_ELEMS;
            int k0 = it << 5;
            // A: 128 rows x 32 cols. Each thread: row ar0, cols ac0..ac0+15 (2 cp16 each for hi/lo)
            {
                long ga = (long)(bm + ar0) * K + k0 + ac0;
                cp16(smem_u32(st + ar0 * LDA_P + ac0), Ah + ga);
                cp16(smem_u32(st + ar0 * LDA_P + ac0 + 8), Ah + ga + 8);
                cp16(smem_u32(st + OFF_AL + ar0 * LDA_P + ac0), Al + ga);
                cp16(smem_u32(st + OFF_AL + ar0 * LDA_P + ac0 + 8), Al + ga + 8);
            }
            // B: 32 rows x 128 cols. Each thread: rows br0 and br0+16, cols bc0..bc0+7
            {
                long gb0 = (long)(k0 + br0) * N + bn + bc0;
                long gb1 = (long)(k0 + br0 + 16) * N + bn + bc0;
                cp16(smem_u32(st + OFF_BH + br0 * LDB_P + bc0), Bhz + gb0);
                cp16(smem_u32(st + OFF_BH + (br0 + 16) * LDB_P + bc0), Bhz + gb1);
                cp16(smem_u32(st + OFF_BL + br0 * LDB_P + bc0), Blz + gb0);
                cp16(smem_u32(st + OFF_BL + (br0 + 16) * LDB_P + bc0), Blz + gb1);
            }
            cp_commit();
        }
        if (it == 0) continue;
        if (it < nIter) cp_wait1(); else cp_wait0();
        __syncthreads();

        unsigned short* cur = smem + ((it - 1) & 1) * STAGE_ELEMS;
#pragma unroll
        for (int ks = 0; ks < 32; ks += 16) {
            unsigned afh[4][4], afl[4][4], bfh[4][2], bfl[4][2];
#pragma unroll
            for (int mi = 0; mi < 4; mi++) {
                int row = m0 + mi * 16 + (lane & 15);
                int col = ks + (lane >> 4) * 8;
                ldsm4(afh[mi][0], afh[mi][1], afh[mi][2], afh[mi][3],
                      smem_u32(cur + row * LDA_P + col));
                ldsm4(afl[mi][0], afl[mi][1], afl[mi][2], afl[mi][3],
                      smem_u32(cur + OFF_AL + row * LDA_P + col));
            }
#pragma unroll
            for (int ni = 0; ni < 4; ni++) {
                int row = ks + (lane & 15);
                int col = n0 + ni * 8;
                ldsm2t(bfh[ni][0], bfh[ni][1], smem_u32(cur + OFF_BH + row * LDB_P + col));
                ldsm2t(bfl[ni][0], bfl[ni][1], smem_u32(cur + OFF_BL + row * LDB_P + col));
            }
#pragma unroll
            for (int mi = 0; mi < 4; mi++) {
#pragma unroll
                for (int ni = 0; ni < 4; ni++) {
                    mma16816(acc[mi][ni], afh[mi], bfh[ni]);
                    mma16816(acc[mi][ni], afh[mi], bfl[ni]);
                    mma16816(acc[mi][ni], afl[mi], bfh[ni]);
                }
            }
        }
        __syncthreads();
    }

    // epilogue: thread owns rows (m0+mi*16 + lane/4 [+8]), cols (n0+ni*8 + (lane%4)*2)
    const int r4 = lane >> 2;
    const int c2 = (lane & 3) * 2;
#pragma unroll
    for (int mi = 0; mi < 4; mi++) {
#pragma unroll
        for (int ni = 0; ni < 4; ni++) {
            int col = bn + n0 + ni * 8 + c2;
#pragma unroll
            for (int hf = 0; hf < 2; hf++) {
                int row = bm + m0 + mi * 16 + r4 + hf * 8;
                float v0 = acc[mi][ni][hf * 2 + 0];
                float v1 = acc[mi][ni][hf * 2 + 1];
                if (bias_mode == 1) { v0 += bias[col]; v1 += bias[col + 1]; }
                if (bias_mode == 2) { float bv = bias[row]; v0 += bv; v1 += bv; }
                if (addz) {
                    v0 += addz[(long)row * N + col];
                    v1 += addz[(long)row * N + col + 1];
                }
                float2 ov;
                ov.x = v0; ov.y = v1;
                *(float2*)(Cz + (long)row * N + col) = ov;
            }
        }
    }
}

// ---------------- RoPE ----------------
__device__ __forceinline__ float rope_pval(int l, int m)
{
    int i = (m < 32) ? m : m - 32;
    float inv = powf(10000.f, -(float)(2 * i) / 64.f);
    float ang = (float)l * inv;
    return (m < 32) ? cosf(ang) : sinf(ang);
}

__global__ __launch_bounds__(256) void rope_kernel(const float* __restrict__ in, float* __restrict__ out)
{
    int idx = blockIdx.x * blockDim.x + threadIdx.x;
    if (idx >= Bb * Ls * Hh * 32) return;
    int j = idx & 31;
    int h = (idx >> 5) & (Hh - 1);
    int bl = idx >> 9;
    int l = bl & (Ls - 1);
    long base = (long)bl * Ds + h * HDd;
    float xe = in[base + 2 * j];
    float xo = in[base + 2 * j + 1];
    float c = rope_pval(l, 2 * j);
    float s = rope_pval(l, 2 * j + 1);
    out[base + j] = xe * c - xo * s;
    out[base + 32 + j] = xe * s + xo * c;
}

// ---------------- fused attention (flash-style, ALiBi, HD=64) ----------------
#define ATTN_SMEM_FLOATS (64*64 + 3*64*68 + 64)

__global__ __launch_bounds__(256) void attn_kernel(
    const float* __restrict__ Q, const float* __restrict__ Kp,
    const float* __restrict__ Vp, float* __restrict__ O)
{
    extern __shared__ float sm[];
    float* sq = sm;
    float* sk = sq + 64 * 64;
    float* sv = sk + 64 * 68;
    float* ss = sv + 64 * 68;
    float* salpha = ss + 64 * 68;

    int tid = threadIdx.x;
    int bh = blockIdx.y;
    int b = bh >> 4;
    int h = bh & 15;
    int q0 = blockIdx.x * 64;
    int hb = h * HDd;
    float slope = exp2f(-0.5f * (float)h);

    {
        int r = tid >> 4;
        int d0 = (tid & 15) * 4;
#pragma unroll
        for (int cc = 0; cc < 4; cc++) {
            int rr = r + cc * 16;
            float4 v = *(const float4*)&Q[((long)(b * Ls + q0 + rr)) * Ds + hb + d0];
            *(float4*)&sq[rr * 64 + d0] = v;
        }
    }

    int ty = tid >> 4, tx = tid & 15;
    int r0 = ty * 4, c0 = tx * 4;
    int srow = tid >> 2, spart = tid & 3;

    float acc_o[4][4];
#pragma unroll
    for (int i = 0; i < 4; i++)
#pragma unroll
        for (int j = 0; j < 4; j++) acc_o[i][j] = 0.f;

    float mrow = -1e30f, lrow = 0.f;

    for (int k0 = 0; k0 < Ls; k0 += 64) {
        __syncthreads();
        {
            int c = tid >> 4;
            int d0 = (tid & 15) * 4;
#pragma unroll
            for (int cc = 0; cc < 4; cc++) {
                int rr = c + cc * 16;
                long gidx = ((long)(b * Ls + k0 + rr)) * Ds + hb + d0;
                *(float4*)&sk[rr * 68 + d0] = *(const float4*)&Kp[gidx];
                *(float4*)&sv[rr * 68 + d0] = *(const float4*)&Vp[gidx];
            }
        }
        __syncthreads();

        float acc[4][4];
#pragma unroll
        for (int i = 0; i < 4; i++)
#pragma unroll
            for (int j = 0; j < 4; j++) acc[i][j] = 0.f;

#pragma unroll 4
        for (int d0 = 0; d0 < 64; d0 += 4) {
            float4 a4[4], b4[4];
#pragma unroll
            for (int i = 0; i < 4; i++) a4[i] = *(const float4*)&sq[(r0 + i) * 64 + d0];
#pragma unroll
            for (int j = 0; j < 4; j++) b4[j] = *(const float4*)&sk[(c0 + j) * 68 + d0];
#pragma unroll
            for (int i = 0; i < 4; i++) {
                float ax = a4[i].x, ay = a4[i].y, az = a4[i].z, aw = a4[i].w;
#pragma unroll
                for (int j = 0; j < 4; j++) {
                    acc[i][j] = fmaf(ax, b4[j].x, acc[i][j]);
                    acc[i][j] = fmaf(ay, b4[j].y, acc[i][j]);
                    acc[i][j] = fmaf(az, b4[j].z, acc[i][j]);
                    acc[i][j] = fmaf(aw, b4[j].w, acc[i][j]);
                }
            }
        }
#pragma unroll
        for (int i = 0; i < 4; i++) {
            int qi = q0 + r0 + i;
            float vv0 = acc[i][0] * 0.125f + slope * fmaxf((float)(qi - (k0 + c0 + 0)), 0.f);
            float vv1 = acc[i][1] * 0.125f + slope * fmaxf((float)(qi - (k0 + c0 + 1)), 0.f);
            float vv2 = acc[i][2] * 0.125f + slope * fmaxf((float)(qi - (k0 + c0 + 2)), 0.f);
            float vv3 = acc[i][3] * 0.125f + slope * fmaxf((float)(qi - (k0 + c0 + 3)), 0.f);
            float4 w;
            w.x = vv0; w.y = vv1; w.z = vv2; w.w = vv3;
            *(float4*)&ss[(r0 + i) * 68 + c0] = w;
        }
        __syncthreads();

        {
            int cbase = spart * 16;
            float tmax = -1e30f;
#pragma unroll
            for (int c = 0; c < 16; c++) tmax = fmaxf(tmax, ss[srow * 68 + cbase + c]);
            tmax = fmaxf(tmax, __shfl_xor_sync(0xffffffffu, tmax, 1));
            tmax = fmaxf(tmax, __shfl_xor_sync(0xffffffffu, tmax, 2));
            float mnew = fmaxf(mrow, tmax);
            float alpha = __expf(mrow - mnew);
            float psum = 0.f;
#pragma unroll
            for (int c = 0; c < 16; c++) {
                float p = __expf(ss[srow * 68 + cbase + c] - mnew);
                ss[srow * 68 + cbase + c] = p;
                psum += p;
            }
            psum += __shfl_xor_sync(0xffffffffu, psum, 1);
            psum += __shfl_xor_sync(0xffffffffu, psum, 2);
            lrow = lrow * alpha + psum;
            mrow = mnew;
            if (spart == 0) salpha[srow] = alpha;
        }
        __syncthreads();

        {
            float al0 = salpha[r0 + 0];
            float al1 = salpha[r0 + 1];
            float al2 = salpha[r0 + 2];
            float al3 = salpha[r0 + 3];
#pragma unroll
            for (int j = 0; j < 4; j++) {
                acc_o[0][j] *= al0;
                acc_o[1][j] *= al1;
                acc_o[2][j] *= al2;
                acc_o[3][j] *= al3;
            }
#pragma unroll 4
            for (int cc0 = 0; cc0 < 64; cc0 += 4) {
                float4 p4[4], v4[4];
#pragma unroll
                for (int i = 0; i < 4; i++) p4[i] = *(const float4*)&ss[(r0 + i) * 68 + cc0];
#pragma unroll
                for (int c = 0; c < 4; c++) v4[c] = *(const float4*)&sv[(cc0 + c) * 68 + c0];
#pragma unroll
                for (int i = 0; i < 4; i++) {
                    float px = p4[i].x, py = p4[i].y, pz = p4[i].z, pw = p4[i].w;
                    acc_o[i][0] = fmaf(px, v4[0].x, acc_o[i][0]);
                    acc_o[i][1] = fmaf(px, v4[0].y, acc_o[i][1]);
                    acc_o[i][2] = fmaf(px, v4[0].z, acc_o[i][2]);
                    acc_o[i][3] = fmaf(px, v4[0].w, acc_o[i][3]);
                    acc_o[i][0] = fmaf(py, v4[1].x, acc_o[i][0]);
                    acc_o[i][1] = fmaf(py, v4[1].y, acc_o[i][1]);
                    acc_o[i][2] = fmaf(py, v4[1].z, acc_o[i][2]);
                    acc_o[i][3] = fmaf(py, v4[1].w, acc_o[i][3]);
                    acc_o[i][0] = fmaf(pz, v4[2].x, acc_o[i][0]);
                    acc_o[i][1] = fmaf(pz, v4[2].y, acc_o[i][1]);
                    acc_o[i][2] = fmaf(pz, v4[2].z, acc_o[i][2]);
                    acc_o[i][3] = fmaf(pz, v4[2].w, acc_o[i][3]);
                    acc_o[i][0] = fmaf(pw, v4[3].x, acc_o[i][0]);
                    acc_o[i][1] = fmaf(pw, v4[3].y, acc_o[i][1]);
                    acc_o[i][2] = fmaf(pw, v4[3].z, acc_o[i][2]);
                    acc_o[i][3] = fmaf(pw, v4[3].w, acc_o[i][3]);
                }
            }
        }
    }

    __syncthreads();
    if (spart == 0) salpha[srow] = 1.f / lrow;
    __syncthreads();
#pragma unroll
    for (int i = 0; i < 4; i++) {
        float inv = salpha[r0 + i];
        float4 w;
        w.x = acc_o[i][0] * inv;
        w.y = acc_o[i][1] * inv;
        w.z = acc_o[i][2] * inv;
        w.w = acc_o[i][3] * inv;
        *(float4*)&O[((long)(b * Ls + q0 + r0 + i)) * Ds + hb + c0] = w;
    }
}

// ---------------- LayerNorm (optional residual added AFTER ln) ----------------
__global__ __launch_bounds__(256) void ln_kernel(
    const float* __restrict__ x, const float* __restrict__ g, const float* __restrict__ bb,
    const float* __restrict__ res, float* __restrict__ out)
{
    int row = blockIdx.x;
    const float* xr = x + (long)row * Ds;
    __shared__ float sx[Ds];
    __shared__ float sred[8];
    __shared__ float s_mean, s_rstd;
    int tid = threadIdx.x;

    float s = 0.f;
    for (int i = tid; i < Ds; i += 256) {
        float v = xr[i];
        sx[i] = v;
        s += v;
    }
#pragma unroll
    for (int o = 16; o > 0; o >>= 1) s += __shfl_down_sync(0xffffffffu, s, o);
    if ((tid & 31) == 0) sred[tid >> 5] = s;
    __syncthreads();
    if (tid == 0) {
        float t = 0.f;
        for (int i = 0; i < 8; i++) t += sred[i];
        s_mean = t / (float)Ds;
    }
    __syncthreads();
    float m = s_mean;
    float vs = 0.f;
    for (int i = tid; i < Ds; i += 256) {
        float d = sx[i] - m;
        vs += d * d;
    }
#pragma unroll
    for (int o = 16; o > 0; o >>= 1) vs += __shfl_down_sync(0xffffffffu, vs, o);
    if ((tid & 31) == 0) sred[tid >> 5] = vs;
    __syncthreads();
    if (tid == 0) {
        float t = 0.f;
        for (int i = 0; i < 8; i++) t += sred[i];
        s_rstd = rsqrtf(t / (float)Ds + EPSf);
    }
    __syncthreads();
    float rs = s_rstd;
    for (int i = tid; i < Ds; i += 256) {
        float v = (sx[i] - m) * rs * g[i] + bb[i];
        if (res) v += res[(long)row * Ds + i];
        out[(long)row * Ds + i] = v;
    }
}

// ---------------- GLU ----------------
__global__ __launch_bounds__(256) void glu_kernel(const float* __restrict__ hin, float* __restrict__ out)
{
    long idx = (long)blockIdx.x * blockDim.x + threadIdx.x;
    if (idx >= (long)BLn * Ds) return;
    long row = idx / Ds;
    int d = (int)(idx % Ds);
    float a = hin[row * 2 * Ds + d];
    float bgate = hin[row * 2 * Ds + Ds + d];
    out[idx] = a * (1.f / (1.f + expf(-bgate)));
}

// ---------------- depthwise conv + bn affine + hardswish ----------------
__global__ __launch_bounds__(256) void dwconv_kernel(
    const float* __restrict__ in, const float* __restrict__ w, const float* __restrict__ wb,
    const float* __restrict__ bng, const float* __restrict__ bnb, float* __restrict__ out)
{
    long idx = (long)blockIdx.x * blockDim.x + threadIdx.x;
    if (idx >= (long)BLn * Ds) return;
    long row = idx / Ds;
    int d = (int)(idx % Ds);
    int b = (int)(row / Ls);
    int l = (int)(row % Ls);
    float acc = 0.f;
#pragma unroll
    for (int m = 0; m < 5; m++) {
        int lsl = l + 2 - m;
        if (lsl >= 0 && lsl < Ls)
            acc = fmaf(w[d * 5 + m], in[((long)b * Ls + lsl) * Ds + d], acc);
    }
    float bnscale = rsqrtf(1.f + EPSf);
    float y = (acc + wb[d]) * bnscale * bng[d] + bnb[d];
    float r6 = fminf(fmaxf(y + 3.f, 0.f), 6.f);
    out[idx] = y * r6 * (1.f / 6.f);
}

// ---------------- add broadcast row 0 (per batch) ----------------
__global__ __launch_bounds__(256) void addrow0_kernel(float* __restrict__ io, const float* __restrict__ src)
{
    long idx = (long)blockIdx.x * blockDim.x + threadIdx.x;
    if (idx >= (long)BLn * Ds) return;
    long row = idx / Ds;
    int d = (int)(idx % Ds);
    int b = (int)(row / Ls);
    io[idx] += src[(long)b * Ls * Ds + d];
}

// ---------------- exact GELU (in-place) ----------------
__global__ __launch_bounds__(256) void gelu_kernel(float* __restrict__ x, long n)
{
    long idx = (long)blockIdx.x * blockDim.x + threadIdx.x;
    if (idx >= n) return;
    float v = x[idx];
    x[idx] = 0.5f * v * (1.f + erff(v * 0.70710678118654752f));
}

// ---------------- transpose (LxL) ----------------
__global__ void transpose_kernel(const float* __restrict__ in, float* __restrict__ out, int n)
{
    __shared__ float t[32][33];
    int x = blockIdx.x * 32 + threadIdx.x;
    int y = blockIdx.y * 32 + threadIdx.y;
#pragma unroll
    for (int j = 0; j < 32; j += 8)
        t[threadIdx.y + j][threadIdx.x] = in[(long)(y + j) * n + x];
    __syncthreads();
    x = blockIdx.y * 32 + threadIdx.x;
    y = blockIdx.x * 32 + threadIdx.y;
#pragma unroll
    for (int j = 0; j < 32; j += 8)
        out[(long)(y + j) * n + x] = t[threadIdx.x][threadIdx.y + j];
}

// ---------------- host helpers ----------------
static void run_split(const float* x, unsigned short* hi, unsigned short* lo, long n)
{
    long n4 = n / 4;
    split_kernel<<<(int)((n4 + 255) / 256), 256>>>(x, hi, lo, n4 * 4);
}

static void run_bgemm(const unsigned short* Ah, const unsigned short* Al,
                      const unsigned short* Bh, const unsigned short* Bl,
                      const float* bias, const float* addp, float* C,
                      int M, int N, int K, int batch, long sB, long sC, int bias_mode)
{
    dim3 grid(N / 128, M / 128, batch);
    bgemm_kernel<<<grid, 256, BG_SMEM_BYTES>>>(Ah, Al, Bh, Bl, bias, addp, C,
                                               M, N, K, sB, sC, bias_mode);
}

extern "C" void kernel_launch(void* const* d_in, const int* in_sizes, int n_in,
                              void* d_out, int out_size)
{
    const float* p_memory = (const float*)d_in[0];
    const float* p_wq = (const float*)d_in[1];
    const float* p_bq = (const float*)d_in[2];
    const float* p_wk = (const float*)d_in[3];
    const float* p_bk = (const float*)d_in[4];
    const float* p_wv = (const float*)d_in[5];
    const float* p_bv = (const float*)d_in[6];
    const float* p_wo = (const float*)d_in[7];
    const float* p_bo = (const float*)d_in[8];
    const float* p_n1g = (const float*)d_in[9];
    const float* p_n1b = (const float*)d_in[10];
    const float* p_clng = (const float*)d_in[11];
    const float* p_clnb = (const float*)d_in[12];
    const float* p_pw1w = (const float*)d_in[13];
    const float* p_pw1b = (const float*)d_in[14];
    const float* p_dww = (const float*)d_in[15];
    const float* p_dwb = (const float*)d_in[16];
    const float* p_bng = (const float*)d_in[17];
    const float* p_bnb = (const float*)d_in[18];
    const float* p_pw2w = (const float*)d_in[19];
    const float* p_pw2b = (const float*)d_in[20];
    const float* p_projw = (const float*)d_in[21];
    const float* p_projb = (const float*)d_in[22];
    const float* p_proj2w = (const float*)d_in[23];
    const float* p_proj2b = (const float*)d_in[24];
    const float* p_lin1w = (const float*)d_in[25];
    const float* p_lin1b = (const float*)d_in[26];
    const float* p_lin2w = (const float*)d_in[27];
    const float* p_lin2b = (const float*)d_in[28];
    const float* p_n3g = (const float*)d_in[29];
    const float* p_n3b = (const float*)d_in[30];
    float* p_out = (float*)d_out;

    float* s_stage = 0;
    float* s_q = 0;
    float* s_k = 0;
    float* s_v = 0;
    float* s_attn = 0;
    float* s_tgt2 = 0;
    float* s_mem = 0;
    float* s_ln = 0;
    float* s_h2 = 0;
    float* s_glu = 0;
    float* s_dw = 0;
    float* s_conv = 0;
    float* s_pwT = 0;
    float* s_proj = 0;
    float* s_mem2 = 0;
    float* s_ffn = 0;
    float* s_sum = 0;
    unsigned short* s_ah = 0;
    unsigned short* s_al = 0;
    unsigned short* s_bh = 0;
    unsigned short* s_bl = 0;
    cudaGetSymbolAddress((void**)&s_stage, g_stage);
    cudaGetSymbolAddress((void**)&s_q, g_q);
    cudaGetSymbolAddress((void**)&s_k, g_k);
    cudaGetSymbolAddress((void**)&s_v, g_v);
    cudaGetSymbolAddress((void**)&s_attn, g_attn);
    cudaGetSymbolAddress((void**)&s_tgt2, g_tgt2);
    cudaGetSymbolAddress((void**)&s_mem, g_mem);
    cudaGetSymbolAddress((void**)&s_ln, g_ln);
    cudaGetSymbolAddress((void**)&s_h2, g_h2);
    cudaGetSymbolAddress((void**)&s_glu, g_glu);
    cudaGetSymbolAddress((void**)&s_dw, g_dw);
    cudaGetSymbolAddress((void**)&s_conv, g_conv);
    cudaGetSymbolAddress((void**)&s_pwT, g_pwT);
    cudaGetSymbolAddress((void**)&s_proj, g_proj);
    cudaGetSymbolAddress((void**)&s_mem2, g_mem2);
    cudaGetSymbolAddress((void**)&s_ffn, g_ffn);
    cudaGetSymbolAddress((void**)&s_sum, g_sum);
    cudaGetSymbolAddress((void**)&s_ah, g_ah);
    cudaGetSymbolAddress((void**)&s_al, g_al);
    cudaGetSymbolAddress((void**)&s_bh, g_bh);
    cudaGetSymbolAddress((void**)&s_bl, g_bl);

    cudaFuncSetAttribute(attn_kernel, cudaFuncAttributeMaxDynamicSharedMemorySize,
                         ATTN_SMEM_FLOATS * (int)sizeof(float));
    cudaFuncSetAttribute(bgemm_kernel, cudaFuncAttributeMaxDynamicSharedMemorySize,
                         BG_SMEM_BYTES);

    const long eBLD = (long)BLn * Ds;
    int ew_grid = (int)((eBLD + 255) / 256);
    int rope_grid = (Bb * Ls * Hh * 32) / 256;

    // q/k/v projections + RoPE
    run_split(p_memory, s_ah, s_al, eBLD);
    run_split(p_wq, s_bh, s_bl, (long)Ds * Ds);
    run_bgemm(s_ah, s_al, s_bh, s_bl, p_bq, 0, s_stage, BLn, Ds, Ds, 1, 0, 0, 1);
    rope_kernel<<<rope_grid, 256>>>(s_stage, s_q);
    run_split(p_wk, s_bh, s_bl, (long)Ds * Ds);
    run_bgemm(s_ah, s_al, s_bh, s_bl, p_bk, 0, s_stage, BLn, Ds, Ds, 1, 0, 0, 1);
    rope_kernel<<<rope_grid, 256>>>(s_stage, s_k);
    run_split(p_wv, s_bh, s_bl, (long)Ds * Ds);
    run_bgemm(s_ah, s_al, s_bh, s_bl, p_bv, 0, s_v, BLn, Ds, Ds, 1, 0, 0, 1);

    // fused attention
    {
        dim3 agrid(Ls / 64, Bb * Hh);
        attn_kernel<<<agrid, 256, ATTN_SMEM_FLOATS * sizeof(float)>>>(s_q, s_k, s_v, s_attn);
    }

    // output projection, residual + LN
    run_split(s_attn, s_ah, s_al, eBLD);
    run_split(p_wo, s_bh, s_bl, (long)Ds * Ds);
    run_bgemm(s_ah, s_al, s_bh, s_bl, p_bo, 0, s_tgt2, BLn, Ds, Ds, 1, 0, 0, 1);
    ln_kernel<<<BLn, 256>>>(s_tgt2, p_n1g, p_n1b, p_memory, s_mem);

    // conv block
    ln_kernel<<<BLn, 256>>>(s_mem, p_clng, p_clnb, 0, s_ln);
    run_split(s_ln, s_ah, s_al, eBLD);
    run_split(p_pw1w, s_bh, s_bl, (long)Ds * 2 * Ds);
    run_bgemm(s_ah, s_al, s_bh, s_bl, p_pw1b, 0, s_h2, BLn, 2 * Ds, Ds, 1, 0, 0, 1);
    glu_kernel<<<ew_grid, 256>>>(s_h2, s_glu);
    dwconv_kernel<<<ew_grid, 256>>>(s_glu, p_dww, p_dwb, p_bng, p_bnb, s_dw);
    run_split(s_dw, s_ah, s_al, eBLD);
    run_split(p_pw2w, s_bh, s_bl, (long)Ds * Ds);
    run_bgemm(s_ah, s_al, s_bh, s_bl, p_pw2b, 0, s_conv, BLn, Ds, Ds, 1, 0, 0, 1);
    addrow0_kernel<<<ew_grid, 256>>>(s_conv, s_mem);

    // proj branch: proj[b,m,d] = sum_l pwT[m,l] * mem[b,l,d] + proj_b[m]
    {
        dim3 tgrid(Ls / 32, Ls / 32);
        dim3 tblk(32, 8);
        transpose_kernel<<<tgrid, tblk>>>(p_projw, s_pwT, Ls);
    }
    run_split(s_pwT, s_ah, s_al, (long)Ls * Ls);
    run_split(s_mem, s_bh, s_bl, eBLD);
    run_bgemm(s_ah, s_al, s_bh, s_bl, p_projb, 0, s_proj, Ls, Ds, Ls, Bb,
              (long)Ls * Ds, (long)Ls * Ds, 2);
    run_split(s_proj, s_ah, s_al, eBLD);
    run_split(p_proj2w, s_bh, s_bl, (long)Ds * Ds);
    run_bgemm(s_ah, s_al, s_bh, s_bl, p_proj2b, s_conv, s_mem2, BLn, Ds, Ds, 1, 0, 0, 1);

    // FFN
    run_split(s_mem2, s_ah, s_al, eBLD);
    run_split(p_lin1w, s_bh, s_bl, (long)Ds * FFs);
    run_bgemm(s_ah, s_al, s_bh, s_bl, p_lin1b, 0, s_ffn, BLn, FFs, Ds, 1, 0, 0, 1);
    {
        long nt = (long)BLn * FFs;
        gelu_kernel<<<(int)((nt + 255) / 256), 256>>>(s_ffn, nt);
    }
    run_split(s_ffn, s_ah, s_al, (long)BLn * FFs);
    run_split(p_lin2w, s_bh, s_bl, (long)FFs * Ds);
    run_bgemm(s_ah, s_al, s_bh, s_bl, p_lin2b, s_mem2, s_sum, BLn, Ds, FFs, 1, 0, 0, 1);

    // final LN -> output
    ln_kernel<<<BLn, 256>>>(s_sum, p_n3g, p_n3b, 0, p_out);
}